// round 8
// baseline (speedup 1.0000x reference)
#include <cuda_runtime.h>

// ---------------------------------------------------------------------------
// out[t,:] = b + ( Σ_{e->t} f[src_e] ⊗ Y_e ).reshape(512) @ W
//   prepW(0):   pair W rows into u64 Wp[kp][c] = (W[2kp][c], W[2kp+1][c])
//   scatter(1): bucket slot = atomicAdd(cnt[tgt]); write 16B {ev.xyz, src}
//   accum(2):   persistent warps, ~8 targets each; SH per edge; zeroes cnt
//   gemm(3):    cp.async double-buffered, f32x2 over k-pairs  <-- ncu slot
// ---------------------------------------------------------------------------

#define MAX_ATOMS 50176          // 784*64, padded for unguarded tile reads
#define BUCKET    64

__device__ float  g_M[(size_t)MAX_ATOMS * 512];           // ~103 MB
__device__ float4 g_pay[(size_t)MAX_ATOMS * BUCKET];      // 51 MB {vx,vy,vz,src}
__device__ int    g_cnt[MAX_ATOMS] = {};                  // zero-init
__device__ unsigned long long g_Wp[256 * 32];             // paired W

// per-warp int64 detection: odd 32-bit words all zero <=> int64 high halves
static __device__ __forceinline__ int is64_detect(const unsigned int* __restrict__ w) {
    const int lane = threadIdx.x & 31;
    unsigned int v = w[1 + 2 * lane] | w[65 + 2 * lane];
    return __all_sync(0xFFFFFFFFu, v == 0u);
}

// ---- f32x2 helpers --------------------------------------------------------
__device__ __forceinline__ unsigned long long ffma2(unsigned long long a,
                                                    unsigned long long b,
                                                    unsigned long long c) {
    unsigned long long d;
    asm("fma.rn.f32x2 %0, %1, %2, %3;" : "=l"(d) : "l"(a), "l"(b), "l"(c));
    return d;
}
__device__ __forceinline__ unsigned long long pack2(float lo, float hi) {
    unsigned long long d;
    asm("mov.b64 %0, {%1, %2};" : "=l"(d) : "r"(__float_as_uint(lo)), "r"(__float_as_uint(hi)));
    return d;
}
__device__ __forceinline__ float lo2(unsigned long long v) {
    return __uint_as_float((unsigned int)v);
}
__device__ __forceinline__ float hi2(unsigned long long v) {
    return __uint_as_float((unsigned int)(v >> 32));
}

// ---- cp.async helpers -----------------------------------------------------
__device__ __forceinline__ void cp_async16(void* smem_dst, const void* gsrc) {
    unsigned s = (unsigned)__cvta_generic_to_shared(smem_dst);
    asm volatile("cp.async.cg.shared.global [%0], [%1], 16;" :: "r"(s), "l"(gsrc));
}
#define CP_COMMIT()  asm volatile("cp.async.commit_group;")
#define CP_WAIT(N)   asm volatile("cp.async.wait_group %0;" :: "n"(N))

// --- k0: pre-pair W: Wp[kp*32+c] = (W[2kp][c], W[2kp+1][c]) ----------------
__global__ void prepW_kernel(const float* __restrict__ W) {
    const int i = blockIdx.x * blockDim.x + threadIdx.x;   // 0..8191
    if (i < 256 * 32) {
        const int kp = i >> 5;
        const int c  = i & 31;
        g_Wp[i] = pack2(W[(2 * kp) * 32 + c], W[(2 * kp + 1) * 32 + c]);
    }
}

// --- k1: scatter: bucket payload {ev.xyz, src} -----------------------------
__global__ void scatter_kernel(const int* __restrict__ idx,
                               const float* __restrict__ ev, int n_edges) {
    const int is64 = is64_detect((const unsigned int*)idx);
    const int stride = is64 ? 2 : 1;
    const int* __restrict__ sb = idx;
    const int* __restrict__ tb = idx + (size_t)n_edges * stride;
    int gid = blockIdx.x * blockDim.x + threadIdx.x;
    for (int e = gid; e < n_edges; e += gridDim.x * blockDim.x) {
        const int src = sb[(size_t)e * stride];
        const int tgt = tb[(size_t)e * stride];
        int pos = atomicAdd(&g_cnt[tgt], 1);
        if (pos >= BUCKET) pos = BUCKET - 1;   // statistically unreachable
        g_pay[(size_t)tgt * BUCKET + pos] =
            make_float4(ev[(size_t)e * 3 + 0],
                        ev[(size_t)e * 3 + 1],
                        ev[(size_t)e * 3 + 2],
                        __int_as_float(src));
    }
}

// --- k2: accum: persistent warps; lane = h; SH recomputed per edge ---------
__global__ void accum_kernel(const float* __restrict__ f, int n_atoms) {
    const int lane   = threadIdx.x & 31;
    const int warpid = (int)((blockIdx.x * blockDim.x + threadIdx.x) >> 5);
    const int nwarps = (int)((gridDim.x * blockDim.x) >> 5);

    for (int t = warpid; t < n_atoms; t += nwarps) {
        int cnt = g_cnt[t];
        if (cnt > BUCKET) cnt = BUCKET;
        if (lane == 0) g_cnt[t] = 0;          // fold cleanup in

        float m[16];
#pragma unroll
        for (int i = 0; i < 16; i++) m[i] = 0.f;

        if (cnt > 0) {
            const float4* __restrict__ base = &g_pay[(size_t)t * BUCKET];

            float4 pc = base[0];
            float  fc = __ldg(f + (size_t)__float_as_int(pc.w) * 32 + lane);

            for (int p = 0; p < cnt; p++) {
                const int    pn  = (p + 1 < cnt) ? (p + 1) : p;
                const float4 pnx = base[pn];
                const float  fn  = __ldg(f + (size_t)__float_as_int(pnx.w) * 32 + lane);

                const float vx = pc.x, vy = pc.y, vz = pc.z;
                const float r   = sqrtf(vx * vx + vy * vy + vz * vz);
                const float inv = 1.0f / fmaxf(r, 1e-12f);
                const float x = vx * inv, y = vy * inv, z = vz * inv;
                const float x2 = x * x, y2 = y * y, z2 = z * z;

                m[0]  = fmaf(fc, 0.28209479177387814f, m[0]);
                m[1]  = fmaf(fc, 0.4886025119029199f * y, m[1]);
                m[2]  = fmaf(fc, 0.4886025119029199f * z, m[2]);
                m[3]  = fmaf(fc, 0.4886025119029199f * x, m[3]);
                m[4]  = fmaf(fc, 1.0925484305920792f * x * y, m[4]);
                m[5]  = fmaf(fc, 1.0925484305920792f * y * z, m[5]);
                m[6]  = fmaf(fc, 0.31539156525252005f * (3.0f * z2 - 1.0f), m[6]);
                m[7]  = fmaf(fc, 1.0925484305920792f * x * z, m[7]);
                m[8]  = fmaf(fc, 0.5462742152960396f * (x2 - y2), m[8]);
                m[9]  = fmaf(fc, 0.5900435899266435f * y * (3.0f * x2 - y2), m[9]);
                m[10] = fmaf(fc, 2.890611442640554f * x * y * z, m[10]);
                m[11] = fmaf(fc, 0.4570457994644658f * y * (5.0f * z2 - 1.0f), m[11]);
                m[12] = fmaf(fc, 0.3731763325901154f * z * (5.0f * z2 - 3.0f), m[12]);
                m[13] = fmaf(fc, 0.4570457994644658f * x * (5.0f * z2 - 1.0f), m[13]);
                m[14] = fmaf(fc, 1.445305721320277f * z * (x2 - y2), m[14]);
                m[15] = fmaf(fc, 0.5900435899266435f * x * (x2 - 3.0f * y2), m[15]);

                pc = pnx;
                fc = fn;
            }
        }

        float4* dst = reinterpret_cast<float4*>(g_M + (size_t)t * 512 + lane * 16);
        dst[0] = make_float4(m[0],  m[1],  m[2],  m[3]);
        dst[1] = make_float4(m[4],  m[5],  m[6],  m[7]);
        dst[2] = make_float4(m[8],  m[9],  m[10], m[11]);
        dst[3] = make_float4(m[12], m[13], m[14], m[15]);
    }
}

// --- k3: GEMM v4: f32x2 over k-pairs, paired W, cp.async double-buffer -----
// Block 128 threads, tile GT=64 rows x 32 c; thread = 4 rows x 4 cols.
// rows: tyg + 16j (consecutive tyg in warp -> conflict-free LDS of M pairs)
// cols: tx + 8ci  (consecutive tx in warp  -> conflict-free LDS of W pairs)
#define GT   64
#define MSP  36     // Ms row stride in floats (144B: 16B-aligned, banks +4/row)
#define WSP  34     // Wp_s row stride in u64  (272B: 16B-aligned)
__global__ void __launch_bounds__(128) gemm_kernel(
        const float* __restrict__ b,
        float* __restrict__ out, int n_atoms) {
    __shared__ float Ms[2][GT][MSP];
    __shared__ unsigned long long Wp_s[2][16][WSP];

    const int tid = threadIdx.x;         // 0..127
    const int tx  = tid & 7;
    const int tyg = tid >> 3;            // 0..15
    const int t0  = blockIdx.x * GT;

    auto load_chunk = [&](int chunk, int buf) {
        const int k0  = chunk * 32;
        const int kp0 = chunk * 16;
#pragma unroll
        for (int i = 0; i < 4; i++) {            // 512 x 16B: M tile 64x32
            const int v    = tid + i * 128;
            const int row  = v >> 3;
            const int col4 = v & 7;
            cp_async16(&Ms[buf][row][col4 * 4],
                       g_M + (size_t)(t0 + row) * 512 + k0 + col4 * 4);
        }
#pragma unroll
        for (int i = 0; i < 2; i++) {            // 256 x 16B: Wp chunk 16x32 u64
            const int v  = tid + i * 128;
            const int r  = v >> 4;
            const int cc = (v & 15) * 2;
            cp_async16(&Wp_s[buf][r][cc], g_Wp + (kp0 + r) * 32 + cc);
        }
    };

    unsigned long long acc[4][4];        // [row j][col ci], (even-k, odd-k) sums
#pragma unroll
    for (int j = 0; j < 4; j++)
#pragma unroll
        for (int i = 0; i < 4; i++) acc[j][i] = 0ull;

    load_chunk(0, 0);
    CP_COMMIT();

#pragma unroll 1
    for (int c = 0; c < 16; c++) {
        const int buf = c & 1;
        if (c + 1 < 16) {
            load_chunk(c + 1, buf ^ 1);
            CP_COMMIT();
            CP_WAIT(1);
        } else {
            CP_WAIT(0);
        }
        __syncthreads();

#pragma unroll
        for (int kp = 0; kp < 16; kp++) {
            unsigned long long a[4];
#pragma unroll
            for (int j = 0; j < 4; j++)
                a[j] = *reinterpret_cast<const unsigned long long*>(
                    &Ms[buf][tyg + 16 * j][2 * kp]);
            unsigned long long w[4];
#pragma unroll
            for (int ci = 0; ci < 4; ci++)
                w[ci] = Wp_s[buf][kp][tx + 8 * ci];
#pragma unroll
            for (int j = 0; j < 4; j++)
#pragma unroll
                for (int ci = 0; ci < 4; ci++)
                    acc[j][ci] = ffma2(a[j], w[ci], acc[j][ci]);
        }
        __syncthreads();
    }

#pragma unroll
    for (int ci = 0; ci < 4; ci++) {
        const int col = tx + 8 * ci;
        const float bc = b[col];
#pragma unroll
        for (int j = 0; j < 4; j++) {
            const int t = t0 + tyg + 16 * j;
            if (t < n_atoms)
                out[(size_t)t * 32 + col] = lo2(acc[j][ci]) + hi2(acc[j][ci]) + bc;
        }
    }
}

extern "C" void kernel_launch(void* const* d_in, const int* in_sizes, int n_in,
                              void* d_out, int out_size) {
    const float* f   = (const float*)d_in[0];   // [n_atoms,32]
    const float* ev  = (const float*)d_in[1];   // [n_edges,3]
    const int*   idx = (const int*)d_in[2];     // [2,n_edges] int32 or int64
    const float* W   = (const float*)d_in[3];   // [512,32]
    const float* b   = (const float*)d_in[4];   // [32]
    float* out = (float*)d_out;

    const int n_atoms = in_sizes[0] / 32;
    const int n_edges = in_sizes[1] / 3;

    prepW_kernel<<<32, 256>>>(W);

    scatter_kernel<<<1184, 256>>>(idx, ev, n_edges);

    accum_kernel<<<782, 256>>>(f, n_atoms);

    const int gblocks = (n_atoms + GT - 1) / GT;
    gemm_kernel<<<gblocks, 128>>>(b, out, n_atoms);
}

// round 9
// speedup vs baseline: 1.4387x; 1.4387x over previous
#include <cuda_runtime.h>

// ---------------------------------------------------------------------------
// out[t,:] = b + ( Σ_{e->t} f[src_e] ⊗ Y_e ).reshape(512) @ W
//   prepW(0):    pair W rows into u64 Wp[kp][c] = (W[2kp][c], W[2kp+1][c])
//   scatterA(1): edges [0, n/2)   bucket write 16B {ev.xyz, src}
//   scatterB(2): edges [n/2, n)
//   accum(3):    one warp per target; SH per edge     <-- ncu slot
//   cleanup(4):  re-zero cnt
//   gemm(5):     cp.async double-buffered, f32x2 over k-pairs
// ---------------------------------------------------------------------------

#define MAX_ATOMS 50176          // 784*64, padded for unguarded tile reads
#define BUCKET    64

__device__ float  g_M[(size_t)MAX_ATOMS * 512];           // ~103 MB
__device__ float4 g_pay[(size_t)MAX_ATOMS * BUCKET];      // 51 MB {vx,vy,vz,src}
__device__ int    g_cnt[MAX_ATOMS] = {};                  // zero-init
__device__ unsigned long long g_Wp[256 * 32];             // paired W

// per-warp int64 detection: odd 32-bit words all zero <=> int64 high halves
static __device__ __forceinline__ int is64_detect(const unsigned int* __restrict__ w) {
    const int lane = threadIdx.x & 31;
    unsigned int v = w[1 + 2 * lane] | w[65 + 2 * lane];
    return __all_sync(0xFFFFFFFFu, v == 0u);
}

// ---- f32x2 helpers --------------------------------------------------------
__device__ __forceinline__ unsigned long long ffma2(unsigned long long a,
                                                    unsigned long long b,
                                                    unsigned long long c) {
    unsigned long long d;
    asm("fma.rn.f32x2 %0, %1, %2, %3;" : "=l"(d) : "l"(a), "l"(b), "l"(c));
    return d;
}
__device__ __forceinline__ unsigned long long pack2(float lo, float hi) {
    unsigned long long d;
    asm("mov.b64 %0, {%1, %2};" : "=l"(d) : "r"(__float_as_uint(lo)), "r"(__float_as_uint(hi)));
    return d;
}
__device__ __forceinline__ float lo2(unsigned long long v) {
    return __uint_as_float((unsigned int)v);
}
__device__ __forceinline__ float hi2(unsigned long long v) {
    return __uint_as_float((unsigned int)(v >> 32));
}

// ---- cp.async helpers -----------------------------------------------------
__device__ __forceinline__ void cp_async16(void* smem_dst, const void* gsrc) {
    unsigned s = (unsigned)__cvta_generic_to_shared(smem_dst);
    asm volatile("cp.async.cg.shared.global [%0], [%1], 16;" :: "r"(s), "l"(gsrc));
}
#define CP_COMMIT()  asm volatile("cp.async.commit_group;")
#define CP_WAIT(N)   asm volatile("cp.async.wait_group %0;" :: "n"(N))

// --- k0: pre-pair W: Wp[kp*32+c] = (W[2kp][c], W[2kp+1][c]) ----------------
__global__ void prepW_kernel(const float* __restrict__ W) {
    const int i = blockIdx.x * blockDim.x + threadIdx.x;   // 0..8191
    if (i < 256 * 32) {
        const int kp = i >> 5;
        const int c  = i & 31;
        g_Wp[i] = pack2(W[(2 * kp) * 32 + c], W[(2 * kp + 1) * 32 + c]);
    }
}

// --- k1/k2: scatter half-range: bucket payload {ev.xyz, src} ---------------
__global__ void scatter_kernel(const int* __restrict__ idx,
                               const float* __restrict__ ev,
                               int e0, int e1, int n_edges) {
    const int is64 = is64_detect((const unsigned int*)idx);
    const int stride = is64 ? 2 : 1;
    const int* __restrict__ sb = idx;
    const int* __restrict__ tb = idx + (size_t)n_edges * stride;
    int gid = blockIdx.x * blockDim.x + threadIdx.x;
    for (int e = e0 + gid; e < e1; e += gridDim.x * blockDim.x) {
        const int src = sb[(size_t)e * stride];
        const int tgt = tb[(size_t)e * stride];
        int pos = atomicAdd(&g_cnt[tgt], 1);
        if (pos >= BUCKET) pos = BUCKET - 1;   // statistically unreachable
        g_pay[(size_t)tgt * BUCKET + pos] =
            make_float4(ev[(size_t)e * 3 + 0],
                        ev[(size_t)e * 3 + 1],
                        ev[(size_t)e * 3 + 2],
                        __int_as_float(src));
    }
}

// --- k3: accum: one warp per target; lane = h; SH recomputed per edge ------
__global__ void accum_kernel(const float* __restrict__ f, int n_atoms) {
    const int lane = threadIdx.x & 31;
    const int t = (int)((blockIdx.x * blockDim.x + threadIdx.x) >> 5);
    if (t >= n_atoms) return;

    int cnt = g_cnt[t];
    if (cnt > BUCKET) cnt = BUCKET;

    float m[16];
#pragma unroll
    for (int i = 0; i < 16; i++) m[i] = 0.f;

    if (cnt > 0) {
        const float4* __restrict__ base = &g_pay[(size_t)t * BUCKET];

        float4 pc = base[0];
        float  fc = __ldg(f + (size_t)__float_as_int(pc.w) * 32 + lane);

        for (int p = 0; p < cnt; p++) {
            const int    pn  = (p + 1 < cnt) ? (p + 1) : p;
            const float4 pnx = base[pn];
            const float  fn  = __ldg(f + (size_t)__float_as_int(pnx.w) * 32 + lane);

            const float vx = pc.x, vy = pc.y, vz = pc.z;
            const float r   = sqrtf(vx * vx + vy * vy + vz * vz);
            const float inv = 1.0f / fmaxf(r, 1e-12f);
            const float x = vx * inv, y = vy * inv, z = vz * inv;
            const float x2 = x * x, y2 = y * y, z2 = z * z;

            m[0]  = fmaf(fc, 0.28209479177387814f, m[0]);
            m[1]  = fmaf(fc, 0.4886025119029199f * y, m[1]);
            m[2]  = fmaf(fc, 0.4886025119029199f * z, m[2]);
            m[3]  = fmaf(fc, 0.4886025119029199f * x, m[3]);
            m[4]  = fmaf(fc, 1.0925484305920792f * x * y, m[4]);
            m[5]  = fmaf(fc, 1.0925484305920792f * y * z, m[5]);
            m[6]  = fmaf(fc, 0.31539156525252005f * (3.0f * z2 - 1.0f), m[6]);
            m[7]  = fmaf(fc, 1.0925484305920792f * x * z, m[7]);
            m[8]  = fmaf(fc, 0.5462742152960396f * (x2 - y2), m[8]);
            m[9]  = fmaf(fc, 0.5900435899266435f * y * (3.0f * x2 - y2), m[9]);
            m[10] = fmaf(fc, 2.890611442640554f * x * y * z, m[10]);
            m[11] = fmaf(fc, 0.4570457994644658f * y * (5.0f * z2 - 1.0f), m[11]);
            m[12] = fmaf(fc, 0.3731763325901154f * z * (5.0f * z2 - 3.0f), m[12]);
            m[13] = fmaf(fc, 0.4570457994644658f * x * (5.0f * z2 - 1.0f), m[13]);
            m[14] = fmaf(fc, 1.445305721320277f * z * (x2 - y2), m[14]);
            m[15] = fmaf(fc, 0.5900435899266435f * x * (x2 - 3.0f * y2), m[15]);

            pc = pnx;
            fc = fn;
        }
    }

    float4* dst = reinterpret_cast<float4*>(g_M + (size_t)t * 512 + lane * 16);
    dst[0] = make_float4(m[0],  m[1],  m[2],  m[3]);
    dst[1] = make_float4(m[4],  m[5],  m[6],  m[7]);
    dst[2] = make_float4(m[8],  m[9],  m[10], m[11]);
    dst[3] = make_float4(m[12], m[13], m[14], m[15]);
}

// --- k4: cleanup: re-zero counters for the next call -----------------------
__global__ void cleanup_kernel(int n_atoms) {
    int gid = blockIdx.x * blockDim.x + threadIdx.x;
    for (int i = gid; i < n_atoms; i += gridDim.x * blockDim.x) g_cnt[i] = 0;
}

// --- k5: GEMM v4: f32x2 over k-pairs, paired W, cp.async double-buffer -----
#define GT   64
#define MSP  36
#define WSP  34
__global__ void __launch_bounds__(128) gemm_kernel(
        const float* __restrict__ b,
        float* __restrict__ out, int n_atoms) {
    __shared__ float Ms[2][GT][MSP];
    __shared__ unsigned long long Wp_s[2][16][WSP];

    const int tid = threadIdx.x;         // 0..127
    const int tx  = tid & 7;
    const int tyg = tid >> 3;            // 0..15
    const int t0  = blockIdx.x * GT;

    auto load_chunk = [&](int chunk, int buf) {
        const int k0  = chunk * 32;
        const int kp0 = chunk * 16;
#pragma unroll
        for (int i = 0; i < 4; i++) {
            const int v    = tid + i * 128;
            const int row  = v >> 3;
            const int col4 = v & 7;
            cp_async16(&Ms[buf][row][col4 * 4],
                       g_M + (size_t)(t0 + row) * 512 + k0 + col4 * 4);
        }
#pragma unroll
        for (int i = 0; i < 2; i++) {
            const int v  = tid + i * 128;
            const int r  = v >> 4;
            const int cc = (v & 15) * 2;
            cp_async16(&Wp_s[buf][r][cc], g_Wp + (kp0 + r) * 32 + cc);
        }
    };

    unsigned long long acc[4][4];
#pragma unroll
    for (int j = 0; j < 4; j++)
#pragma unroll
        for (int i = 0; i < 4; i++) acc[j][i] = 0ull;

    load_chunk(0, 0);
    CP_COMMIT();

#pragma unroll 1
    for (int c = 0; c < 16; c++) {
        const int buf = c & 1;
        if (c + 1 < 16) {
            load_chunk(c + 1, buf ^ 1);
            CP_COMMIT();
            CP_WAIT(1);
        } else {
            CP_WAIT(0);
        }
        __syncthreads();

#pragma unroll
        for (int kp = 0; kp < 16; kp++) {
            unsigned long long a[4];
#pragma unroll
            for (int j = 0; j < 4; j++)
                a[j] = *reinterpret_cast<const unsigned long long*>(
                    &Ms[buf][tyg + 16 * j][2 * kp]);
            unsigned long long w[4];
#pragma unroll
            for (int ci = 0; ci < 4; ci++)
                w[ci] = Wp_s[buf][kp][tx + 8 * ci];
#pragma unroll
            for (int j = 0; j < 4; j++)
#pragma unroll
                for (int ci = 0; ci < 4; ci++)
                    acc[j][ci] = ffma2(a[j], w[ci], acc[j][ci]);
        }
        __syncthreads();
    }

#pragma unroll
    for (int ci = 0; ci < 4; ci++) {
        const int col = tx + 8 * ci;
        const float bc = b[col];
#pragma unroll
        for (int j = 0; j < 4; j++) {
            const int t = t0 + tyg + 16 * j;
            if (t < n_atoms)
                out[(size_t)t * 32 + col] = lo2(acc[j][ci]) + hi2(acc[j][ci]) + bc;
        }
    }
}

extern "C" void kernel_launch(void* const* d_in, const int* in_sizes, int n_in,
                              void* d_out, int out_size) {
    const float* f   = (const float*)d_in[0];   // [n_atoms,32]
    const float* ev  = (const float*)d_in[1];   // [n_edges,3]
    const int*   idx = (const int*)d_in[2];     // [2,n_edges] int32 or int64
    const float* W   = (const float*)d_in[3];   // [512,32]
    const float* b   = (const float*)d_in[4];   // [32]
    float* out = (float*)d_out;

    const int n_atoms = in_sizes[0] / 32;
    const int n_edges = in_sizes[1] / 3;
    const int n_half  = n_edges / 2;

    prepW_kernel<<<32, 256>>>(W);

    scatter_kernel<<<592, 256>>>(idx, ev, 0,      n_half,  n_edges);
    scatter_kernel<<<592, 256>>>(idx, ev, n_half, n_edges, n_edges);

    const int ablocks = (n_atoms * 32 + 255) / 256;
    accum_kernel<<<ablocks, 256>>>(f, n_atoms);

    cleanup_kernel<<<98, 512>>>(n_atoms);

    const int gblocks = (n_atoms + GT - 1) / GT;
    gemm_kernel<<<gblocks, 128>>>(b, out, n_atoms);
}